// round 2
// baseline (speedup 1.0000x reference)
#include <cuda_runtime.h>

#define NB     4
#define DIMC   128
#define NSEQ   16384
#define BNTOK  65536
#define LC     64
#define NCH    256

// ---------------- scratch ----------------
__device__ float g_u [2u*BNTOK*128];
__device__ float g_z [2u*BNTOK*128];
__device__ float g_uc[2u*BNTOK*128];
__device__ float g_dt[2u*BNTOK*128];
__device__ float g_ys[2u*BNTOK*128];
__device__ float g_B [2u*BNTOK*8];
__device__ float g_C [2u*BNTOK*8];
__device__ float g_P [2u*4*NCH*128*8];
__device__ float g_Q [2u*4*NCH*128*8];
__device__ float g_H [2u*4*NCH*128*8];
__device__ float g_Weff[2u*128*128];
__device__ float g_beff[128];

// ---------------- f32x2 helpers ----------------
__device__ __forceinline__ unsigned long long fma2(unsigned long long a, unsigned long long b,
                                                   unsigned long long c) {
    unsigned long long d;
    asm("fma.rn.f32x2 %0, %1, %2, %3;" : "=l"(d) : "l"(a), "l"(b), "l"(c));
    return d;
}
__device__ __forceinline__ unsigned long long pack2(float x, float y) {
    unsigned long long r;
    asm("mov.b64 %0, {%1, %2};" : "=l"(r) : "f"(x), "f"(y));
    return r;
}
__device__ __forceinline__ float2 unpk2(unsigned long long v) {
    float2 r;
    asm("mov.b64 {%0, %1}, %2;" : "=f"(r.x), "=f"(r.y) : "l"(v));
    return r;
}
__device__ __forceinline__ float sigmoidf_fast(float x) { return 1.0f / (1.0f + __expf(-x)); }
__device__ __forceinline__ float softplusf(float x) { return (x > 15.0f) ? x : log1pf(__expf(x)); }

// ---------------- shared GEMM micro-kernel ----------------
// xs: [128][68] feature-major (64 tokens), Ws: [128][128] row-major.
__device__ __forceinline__ void gemm_tile(const float* __restrict__ xs,
                                          const float* __restrict__ Ws,
                                          int t0, int j0,
                                          unsigned long long acc[4][4]) {
#pragma unroll 4
    for (int d = 0; d < 128; ++d) {
        float4 xv = *(const float4*)(xs + d * 68 + t0);
        unsigned long long x0 = pack2(xv.x, xv.x);
        unsigned long long x1 = pack2(xv.y, xv.y);
        unsigned long long x2 = pack2(xv.z, xv.z);
        unsigned long long x3 = pack2(xv.w, xv.w);
        const unsigned long long* wp = (const unsigned long long*)(Ws + d * 128 + j0);
        unsigned long long w0 = wp[0], w1 = wp[1], w2 = wp[2], w3 = wp[3];
        acc[0][0] = fma2(x0, w0, acc[0][0]); acc[0][1] = fma2(x0, w1, acc[0][1]);
        acc[0][2] = fma2(x0, w2, acc[0][2]); acc[0][3] = fma2(x0, w3, acc[0][3]);
        acc[1][0] = fma2(x1, w0, acc[1][0]); acc[1][1] = fma2(x1, w1, acc[1][1]);
        acc[1][2] = fma2(x1, w2, acc[1][2]); acc[1][3] = fma2(x1, w3, acc[1][3]);
        acc[2][0] = fma2(x2, w0, acc[2][0]); acc[2][1] = fma2(x2, w1, acc[2][1]);
        acc[2][2] = fma2(x2, w2, acc[2][2]); acc[2][3] = fma2(x2, w3, acc[2][3]);
        acc[3][0] = fma2(x3, w0, acc[3][0]); acc[3][1] = fma2(x3, w1, acc[3][1]);
        acc[3][2] = fma2(x3, w2, acc[3][2]); acc[3][3] = fma2(x3, w3, acc[3][3]);
    }
}

// ---------------- Kernel 0: Weff precompute ----------------
__global__ void weff_kernel(const float* __restrict__ Wm, const float* __restrict__ bm,
                            const float* __restrict__ Wout, const float* __restrict__ bout) {
    int j = threadIdx.x, r = blockIdx.x, i = blockIdx.y;
    float acc = 0.f;
    for (int k = 0; k < 128; ++k) acc += Wm[i * 16384 + r * 128 + k] * Wout[k * 128 + j];
    g_Weff[i * 16384 + r * 128 + j] = 0.5f * acc;
    if (r == 0 && i == 0) {
        float b = bout[j];
        for (int k = 0; k < 128; ++k) b += 0.5f * (bm[k] + bm[128 + k]) * Wout[k * 128 + j];
        g_beff[j] = b;
    }
}

// ---------------- Kernel 1: LN + input GEMMs ----------------
// grid (1024, 4), block 256, dyn smem 100352 B
extern "C" __global__ void __launch_bounds__(256) ln_gemm_kernel(
    const float* __restrict__ front, const float* __restrict__ back,
    const float* __restrict__ ln0w, const float* __restrict__ ln0b,
    const float* __restrict__ ln1w, const float* __restrict__ ln1b,
    const float* __restrict__ Wx, const float* __restrict__ Wz) {
    extern __shared__ float sm[];
    float* xs = sm;              // 128 x 68
    float* Ws = sm + 128 * 68;   // 128 x 128
    __shared__ float s_red[8][64];
    __shared__ float s_mean[64], s_rstd[64];
    __shared__ float s_lnw[128], s_lnb[128];

    int c = blockIdx.y;
    int dir = c >> 1;
    const float* src = (c == 0 || c == 3) ? front : back;
    const float* lw = (c & 1) ? ln1w + dir * 128 : ln0w + dir * 128;
    const float* lb = (c & 1) ? ln1b + dir * 128 : ln0b + dir * 128;
    const float* W  = ((c & 1) ? Wz : Wx) + dir * 128 * 128;
    float* out = ((c & 1) ? g_z : g_u) + (size_t)dir * BNTOK * 128;

    int g0 = blockIdx.x * 64;
    int b  = g0 >> 14;
    int n0 = g0 & (NSEQ - 1);
    const float* sbase = src + (size_t)b * 128 * NSEQ + n0;
    int tid = threadIdx.x;

#pragma unroll
    for (int it = 0; it < 8; ++it) {
        int idx = tid + it * 256;
        int d = idx >> 4, v = idx & 15;
        *(float4*)(xs + d * 68 + v * 4) = *(const float4*)(sbase + (size_t)d * NSEQ + v * 4);
    }
    if (tid < 128) { s_lnw[tid] = lw[tid]; s_lnb[tid] = lb[tid]; }
#pragma unroll
    for (int it = 0; it < 16; ++it) {
        int idx = tid + it * 256;
        *(float4*)(Ws + idx * 4) = *(const float4*)(W + idx * 4);
    }
    __syncthreads();

    {
        int t = tid & 63, part = tid >> 6;
        float s = 0.f, s2 = 0.f;
        for (int d = part * 32; d < part * 32 + 32; ++d) {
            float x = xs[d * 68 + t];
            s += x; s2 += x * x;
        }
        s_red[part][t] = s;
        s_red[part + 4][t] = s2;
    }
    __syncthreads();
    if (tid < 64) {
        float m = (s_red[0][tid] + s_red[1][tid] + s_red[2][tid] + s_red[3][tid]) * (1.f / 128.f);
        float q = (s_red[4][tid] + s_red[5][tid] + s_red[6][tid] + s_red[7][tid]) * (1.f / 128.f);
        s_mean[tid] = m;
        s_rstd[tid] = rsqrtf(q - m * m + 1e-5f);
    }
    __syncthreads();
#pragma unroll
    for (int it = 0; it < 8; ++it) {
        int idx = tid + it * 256;
        int d = idx >> 4, v = idx & 15, t = v * 4;
        float4 x = *(float4*)(xs + d * 68 + v * 4);
        float w = s_lnw[d], bb = s_lnb[d];
        x.x = (x.x - s_mean[t + 0]) * s_rstd[t + 0] * w + bb;
        x.y = (x.y - s_mean[t + 1]) * s_rstd[t + 1] * w + bb;
        x.z = (x.z - s_mean[t + 2]) * s_rstd[t + 2] * w + bb;
        x.w = (x.w - s_mean[t + 3]) * s_rstd[t + 3] * w + bb;
        *(float4*)(xs + d * 68 + v * 4) = x;
    }
    __syncthreads();

    int jt = tid & 15, tt = tid >> 4;
    int j0 = jt * 8, t0 = tt * 4;
    unsigned long long acc[4][4];
#pragma unroll
    for (int t = 0; t < 4; ++t)
#pragma unroll
        for (int p = 0; p < 4; ++p) acc[t][p] = 0ull;

    gemm_tile(xs, Ws, t0, j0, acc);

#pragma unroll
    for (int t = 0; t < 4; ++t) {
        float2 a0 = unpk2(acc[t][0]), a1 = unpk2(acc[t][1]);
        float2 a2 = unpk2(acc[t][2]), a3 = unpk2(acc[t][3]);
        float4 o0 = {a0.x, a0.y, a1.x, a1.y};
        float4 o1 = {a2.x, a2.y, a3.x, a3.y};
        float* op = out + (size_t)(g0 + t0 + t) * 128 + j0;
        *(float4*)op = o0;
        *(float4*)(op + 4) = o1;
    }
}

// ---------------- Kernel 2: causal depthwise conv + SiLU ----------------
extern "C" __global__ void __launch_bounds__(256) conv_silu_kernel(
    const float* __restrict__ conv_w, const float* __restrict__ conv_b) {
    unsigned idx = blockIdx.x * 256u + threadIdx.x;
    int d = idx & 127;
    int n = (idx >> 7) & (NSEQ - 1);
    int i = idx >> 23;
    const float* w = conv_w + i * 512 + d * 4;
    float acc = conv_b[i * 128 + d];
#pragma unroll
    for (int k = 0; k < 4; ++k) {
        if (n + k >= 3) acc += w[k] * g_u[idx + (unsigned)((k - 3) * 128)];
    }
    g_uc[idx] = acc * sigmoidf_fast(acc);
}

// ---------------- Kernel 3: x_dbl projection -> dt/B/C ----------------
// grid (2048, 2), block 128
extern "C" __global__ void __launch_bounds__(128) proj_kernel(
    const float* __restrict__ Wxproj, const float* __restrict__ Wdt,
    const float* __restrict__ bdt) {
    __shared__ float ucs[32 * 132];
    __shared__ float wxp[128 * 24];
    __shared__ float xd[32 * 25];
    __shared__ float wdts[8 * 128];
    __shared__ float bdts[128];

    int i = blockIdx.y;
    int g0 = blockIdx.x * 32;
    int tid = threadIdx.x;

#pragma unroll
    for (int k = 0; k < 8; ++k) {
        int idx = tid + k * 128;
        int t = idx >> 5, dv = idx & 31;
        *(float4*)(ucs + t * 132 + dv * 4) =
            *(const float4*)(g_uc + ((size_t)i * BNTOK + g0 + t) * 128 + dv * 4);
    }
#pragma unroll
    for (int k = 0; k < 24; ++k) wxp[tid + k * 128] = Wxproj[i * 3072 + tid + k * 128];
#pragma unroll
    for (int k = 0; k < 8; ++k) wdts[tid + k * 128] = Wdt[i * 1024 + tid + k * 128];
    bdts[tid] = bdt[i * 128 + tid];
    __syncthreads();

    {
        int t = tid >> 2, p = tid & 3, j0 = p * 6;
        float a[6];
#pragma unroll
        for (int q = 0; q < 6; ++q) a[q] = 0.f;
        for (int d = 0; d < 128; ++d) {
            float x = ucs[t * 132 + d];
#pragma unroll
            for (int q = 0; q < 6; ++q) a[q] += x * wxp[d * 24 + j0 + q];
        }
#pragma unroll
        for (int q = 0; q < 6; ++q) xd[t * 25 + j0 + q] = a[q];
    }
    __syncthreads();

    {
        int dd = tid;
        for (int t = 0; t < 32; ++t) {
            float acc = bdts[dd];
#pragma unroll
            for (int r = 0; r < 8; ++r) acc += xd[t * 25 + r] * wdts[r * 128 + dd];
            g_dt[((size_t)i * BNTOK + g0 + t) * 128 + dd] = softplusf(acc);
        }
    }
    for (int idx = tid; idx < 512; idx += 128) {
        int t = idx >> 4, q = idx & 15;
        float v = xd[t * 25 + 8 + q];
        size_t gg = ((size_t)i * BNTOK + g0 + t) * 8;
        if (q < 8) g_B[gg + q] = v;
        else       g_C[gg + q - 8] = v;
    }
}

// ---------------- Kernel 4a: per-chunk local scan ----------------
// grid 2048 (= 2*4*256), block 128
extern "C" __global__ void __launch_bounds__(128) scan_a_kernel(const float* __restrict__ A_log) {
    __shared__ float Bs[LC * 8];
    int bx = blockIdx.x;
    int c = bx & (NCH - 1), b = (bx >> 8) & 3, i = bx >> 10;
    int d = threadIdx.x;
    float a[8];
#pragma unroll
    for (int s = 0; s < 8; ++s) a[s] = -__expf(A_log[i * 1024 + d * 8 + s]);

    size_t gtok0 = (size_t)i * BNTOK + b * NSEQ + c * LC;
    for (int k = d; k < LC * 8; k += 128) Bs[k] = g_B[gtok0 * 8 + k];
    __syncthreads();

    float P[8], h[8];
#pragma unroll
    for (int s = 0; s < 8; ++s) { P[s] = 1.f; h[s] = 0.f; }
    const float* dtp = g_dt + gtok0 * 128 + d;
    const float* ucp = g_uc + gtok0 * 128 + d;
#pragma unroll 2
    for (int t = 0; t < LC; ++t) {
        float dtv = dtp[t * 128], ucv = ucp[t * 128];
        float du = dtv * ucv;
#pragma unroll
        for (int s = 0; s < 8; ++s) {
            float dA = __expf(dtv * a[s]);
            P[s] *= dA;
            h[s] = dA * h[s] + du * Bs[t * 8 + s];
        }
    }
    size_t o = ((size_t)((i * 4 + b) * NCH + c)) * 1024 + d * 8;
    *(float4*)(g_P + o)     = make_float4(P[0], P[1], P[2], P[3]);
    *(float4*)(g_P + o + 4) = make_float4(P[4], P[5], P[6], P[7]);
    *(float4*)(g_Q + o)     = make_float4(h[0], h[1], h[2], h[3]);
    *(float4*)(g_Q + o + 4) = make_float4(h[4], h[5], h[6], h[7]);
}

// ---------------- Kernel 4b: chunk combine ----------------
// grid 32, block 256  (8192 = 2*4*128*8 threads)
extern "C" __global__ void __launch_bounds__(256) scan_b_kernel() {
    int idx = blockIdx.x * 256 + threadIdx.x;
    int ib = idx >> 10, ds = idx & 1023;
    size_t base = (size_t)ib * NCH * 1024 + ds;
    float h = 0.f;
    for (int c0 = 0; c0 < NCH; c0 += 8) {
        float P8[8], Q8[8];
#pragma unroll
        for (int k = 0; k < 8; ++k) {
            size_t o = base + (size_t)(c0 + k) * 1024;
            P8[k] = g_P[o]; Q8[k] = g_Q[o];
        }
#pragma unroll
        for (int k = 0; k < 8; ++k) {
            size_t o = base + (size_t)(c0 + k) * 1024;
            g_H[o] = h;
            h = P8[k] * h + Q8[k];
        }
    }
}

// ---------------- Kernel 4c: replay + fused epilogue ----------------
// grid 2048, block 128
extern "C" __global__ void __launch_bounds__(128) scan_c_kernel(
    const float* __restrict__ A_log, const float* __restrict__ Dp) {
    __shared__ float Bs[LC * 8];
    __shared__ float Cs[LC * 8];
    int bx = blockIdx.x;
    int c = bx & (NCH - 1), b = (bx >> 8) & 3, i = bx >> 10;
    int d = threadIdx.x;
    float a[8];
#pragma unroll
    for (int s = 0; s < 8; ++s) a[s] = -__expf(A_log[i * 1024 + d * 8 + s]);
    float dp = Dp[i * 128 + d];

    size_t gtok0 = (size_t)i * BNTOK + b * NSEQ + c * LC;
    for (int k = d; k < LC * 8; k += 128) {
        Bs[k] = g_B[gtok0 * 8 + k];
        Cs[k] = g_C[gtok0 * 8 + k];
    }
    __syncthreads();

    size_t o = ((size_t)((i * 4 + b) * NCH + c)) * 1024 + d * 8;
    float h[8];
    float4 h0 = *(const float4*)(g_H + o);
    float4 h1 = *(const float4*)(g_H + o + 4);
    h[0] = h0.x; h[1] = h0.y; h[2] = h0.z; h[3] = h0.w;
    h[4] = h1.x; h[5] = h1.y; h[6] = h1.z; h[7] = h1.w;

    const float* dtp = g_dt + gtok0 * 128 + d;
    const float* ucp = g_uc + gtok0 * 128 + d;
    const float* zp  = g_z  + gtok0 * 128 + d;
    float* yp        = g_ys + gtok0 * 128 + d;
#pragma unroll 2
    for (int t = 0; t < LC; ++t) {
        float dtv = dtp[t * 128], ucv = ucp[t * 128], zv = zp[t * 128];
        float du = dtv * ucv;
        float y = 0.f;
#pragma unroll
        for (int s = 0; s < 8; ++s) {
            float dA = __expf(dtv * a[s]);
            h[s] = dA * h[s] + du * Bs[t * 8 + s];
            y += h[s] * Cs[t * 8 + s];
        }
        float yy = y + dp * ucv;
        yp[t * 128] = yy * (zv * sigmoidf_fast(zv));
    }
}

// ---------------- Kernel 5: output GEMM (3 accumulated matmuls) ----------------
// grid 1024, block 256, dyn smem 100352 B
extern "C" __global__ void __launch_bounds__(256) out_gemm_kernel(
    const float* __restrict__ front, const float* __restrict__ back,
    const float* __restrict__ Wout, float* __restrict__ outp) {
    extern __shared__ float sm[];
    float* xs = sm;
    float* Ws = sm + 128 * 68;

    int g0 = blockIdx.x * 64;
    int b  = g0 >> 14;
    int n0 = g0 & (NSEQ - 1);
    int tid = threadIdx.x;
    int jt = tid & 15, tt = tid >> 4;
    int j0 = jt * 8, t0 = tt * 4;

    unsigned long long acc[4][4];
#pragma unroll
    for (int t = 0; t < 4; ++t)
#pragma unroll
        for (int p = 0; p < 4; ++p) acc[t][p] = 0ull;

    // phase 0: 0.5*(front+back) @ Wout
    {
        const float* f = front + (size_t)b * 128 * NSEQ + n0;
        const float* g = back  + (size_t)b * 128 * NSEQ + n0;
#pragma unroll
        for (int it = 0; it < 8; ++it) {
            int idx = tid + it * 256;
            int d = idx >> 4, v = idx & 15;
            float4 x = *(const float4*)(f + (size_t)d * NSEQ + v * 4);
            float4 y = *(const float4*)(g + (size_t)d * NSEQ + v * 4);
            x.x = 0.5f * (x.x + y.x); x.y = 0.5f * (x.y + y.y);
            x.z = 0.5f * (x.z + y.z); x.w = 0.5f * (x.w + y.w);
            *(float4*)(xs + d * 68 + v * 4) = x;
        }
#pragma unroll
        for (int it = 0; it < 16; ++it) {
            int idx = tid + it * 256;
            *(float4*)(Ws + idx * 4) = *(const float4*)(Wout + idx * 4);
        }
        __syncthreads();
        gemm_tile(xs, Ws, t0, j0, acc);
        __syncthreads();
    }

    // phases 1,2: y_i @ Weff_i
    for (int i = 0; i < 2; ++i) {
        const float* ysrc = g_ys + ((size_t)i * BNTOK + g0) * 128;
#pragma unroll
        for (int it = 0; it < 8; ++it) {
            int idx = tid + it * 256;
            int t = idx >> 5, dv = idx & 31;
            float4 v = *(const float4*)(ysrc + (size_t)t * 128 + dv * 4);
            xs[(dv * 4 + 0) * 68 + t] = v.x;
            xs[(dv * 4 + 1) * 68 + t] = v.y;
            xs[(dv * 4 + 2) * 68 + t] = v.z;
            xs[(dv * 4 + 3) * 68 + t] = v.w;
        }
#pragma unroll
        for (int it = 0; it < 16; ++it) {
            int idx = tid + it * 256;
            *(float4*)(Ws + idx * 4) = *(const float4*)(g_Weff + i * 16384 + idx * 4);
        }
        __syncthreads();
        gemm_tile(xs, Ws, t0, j0, acc);
        __syncthreads();
    }

    // store channel-major: out[(b*128 + j)*NSEQ + n]
    float* ob = outp + ((size_t)b * 128) * NSEQ + n0 + t0;
#pragma unroll
    for (int p = 0; p < 4; ++p) {
        float2 a0 = unpk2(acc[0][p]), a1 = unpk2(acc[1][p]);
        float2 a2 = unpk2(acc[2][p]), a3 = unpk2(acc[3][p]);
        int j = j0 + 2 * p;
        float be = g_beff[j], bo = g_beff[j + 1];
        float4 v0 = {a0.x + be, a1.x + be, a2.x + be, a3.x + be};
        float4 v1 = {a0.y + bo, a1.y + bo, a2.y + bo, a3.y + bo};
        *(float4*)(ob + (size_t)j * NSEQ) = v0;
        *(float4*)(ob + (size_t)(j + 1) * NSEQ) = v1;
    }
}

// ---------------- launch ----------------
extern "C" void kernel_launch(void* const* d_in, const int* in_sizes, int n_in,
                              void* d_out, int out_size) {
    const float* front  = (const float*)d_in[0];
    const float* back   = (const float*)d_in[1];
    const float* ln0w   = (const float*)d_in[2];
    const float* ln0b   = (const float*)d_in[3];
    const float* ln1w   = (const float*)d_in[4];
    const float* ln1b   = (const float*)d_in[5];
    const float* Wx     = (const float*)d_in[6];
    const float* Wz     = (const float*)d_in[7];
    const float* conv_w = (const float*)d_in[8];
    const float* conv_b = (const float*)d_in[9];
    const float* Wxproj = (const float*)d_in[10];
    const float* Wdt    = (const float*)d_in[11];
    const float* bdt    = (const float*)d_in[12];
    const float* A_log  = (const float*)d_in[13];
    const float* Dp     = (const float*)d_in[14];
    const float* Wout_m = (const float*)d_in[15];
    const float* bout_m = (const float*)d_in[16];
    const float* Wout   = (const float*)d_in[17];
    const float* bout   = (const float*)d_in[18];
    float* out = (float*)d_out;

    const int SMEM1 = (128 * 68 + 128 * 128) * 4;
    cudaFuncSetAttribute(ln_gemm_kernel, cudaFuncAttributeMaxDynamicSharedMemorySize, SMEM1);
    cudaFuncSetAttribute(out_gemm_kernel, cudaFuncAttributeMaxDynamicSharedMemorySize, SMEM1);

    weff_kernel<<<dim3(128, 2), 128>>>(Wout_m, bout_m, Wout, bout);
    ln_gemm_kernel<<<dim3(1024, 4), 256, SMEM1>>>(front, back, ln0w, ln0b, ln1w, ln1b, Wx, Wz);
    conv_silu_kernel<<<65536, 256>>>(conv_w, conv_b);
    proj_kernel<<<dim3(2048, 2), 128>>>(Wxproj, Wdt, bdt);
    scan_a_kernel<<<2048, 128>>>(A_log);
    scan_b_kernel<<<32, 256>>>();
    scan_c_kernel<<<2048, 128>>>(A_log, Dp);
    out_gemm_kernel<<<1024, 256, SMEM1>>>(front, back, Wout, out);
}